// round 6
// baseline (speedup 1.0000x reference)
#include <cuda_runtime.h>
#include <cuda_bf16.h>
#include <math.h>
#include <stdint.h>

// ---------------- problem constants ----------------
#define BATCH 8
#define CHN 3
#define IMG 224
#define PATCH 16
#define GRID 14
#define NPATCH 196
#define SEQ 197
#define DIM 768
#define NHEAD 12
#define HDIM 64
#define NLAYER 12
#define TOPK 32
#define MLPDIM 3072
#define ATT_SCALE 0.125f

#define NROWS (BATCH*SEQ)           // 1576
#define NROWS_P (BATCH*NPATCH)      // 1568

// quantization constants: a16 = ah*254 + al, |a16| <= 32256 = 127*254
#define QMAX 32256.0f
#define INVQ2 9.6112159e-10f        // 1 / 32256^2

// weight element offsets
#define NW_PATCH (DIM*DIM)
#define NW_QKV   (NLAYER*3*DIM*DIM)
#define NW_PROJ  (NLAYER*DIM*DIM)
#define NW_FC1   (NLAYER*MLPDIM*DIM)
#define NW_FC2   (NLAYER*DIM*MLPDIM)
#define OFF_PATCH 0
#define OFF_QKV   (OFF_PATCH + NW_PATCH)
#define OFF_PROJ  (OFF_QKV + NW_QKV)
#define OFF_FC1   (OFF_PROJ + NW_PROJ)
#define OFF_FC2   (OFF_FC1 + NW_FC1)
#define NW_TOTAL  (OFF_FC2 + NW_FC2)

// weight scale (row) offsets
#define WS_PATCH 0
#define WS_QKV   (WS_PATCH + DIM)
#define WS_PROJ  (WS_QKV + NLAYER*3*DIM)
#define WS_FC1   (WS_PROJ + NLAYER*DIM)
#define WS_FC2   (WS_FC1 + NLAYER*MLPDIM)
#define WS_TOTAL (WS_FC2 + NLAYER*DIM)

// ---------------- scratch ----------------
__device__ float  g_h   [NROWS*DIM];
__device__ float  g_qkv [NROWS*3*DIM];
__device__ float  g_mlp [NROWS*MLPDIM];
__device__ int8_t g_xnh8[NROWS*DIM];
__device__ int8_t g_xnl8[NROWS*DIM];
__device__ float  g_xnsc[NROWS];
__device__ int8_t g_ath8[NROWS*DIM];
__device__ int8_t g_atl8[NROWS*DIM];
__device__ float  g_atsc[NROWS];
__device__ int8_t g_mlh8[NROWS*MLPDIM];   // also reused for patchify output
__device__ int8_t g_mll8[NROWS*MLPDIM];
__device__ float  g_mlsc[NROWS];
__device__ int8_t g_wh8[NW_TOTAL];
__device__ int8_t g_wl8[NW_TOTAL];
__device__ float  g_wsc[WS_TOTAL];

// ---------------- helpers ----------------
__device__ __forceinline__ uint32_t smem_u32(const void* p) {
    uint32_t a;
    asm("{ .reg .u64 t; cvta.to.shared.u64 t, %1; cvt.u32.u64 %0, t; }" : "=r"(a) : "l"(p));
    return a;
}
__device__ __forceinline__ void ldmx4(uint32_t& r0, uint32_t& r1, uint32_t& r2, uint32_t& r3,
                                      uint32_t addr) {
    asm volatile("ldmatrix.sync.aligned.m8n8.x4.shared.b16 {%0,%1,%2,%3}, [%4];"
                 : "=r"(r0), "=r"(r1), "=r"(r2), "=r"(r3) : "r"(addr));
}
__device__ __forceinline__ void imma16832(int* d, const uint32_t* a, uint32_t b0, uint32_t b1) {
    asm volatile(
        "mma.sync.aligned.m16n8k32.row.col.s32.s8.s8.s32 "
        "{%0,%1,%2,%3},{%4,%5,%6,%7},{%8,%9},{%0,%1,%2,%3};"
        : "+r"(d[0]), "+r"(d[1]), "+r"(d[2]), "+r"(d[3])
        : "r"(a[0]), "r"(a[1]), "r"(a[2]), "r"(a[3]), "r"(b0), "r"(b1));
}
#define CP16(dst, src, sz) \
    asm volatile("cp.async.cg.shared.global [%0], [%1], 16, %2;" \
                 :: "r"(dst), "l"(src), "r"(sz))
#define CP_COMMIT() asm volatile("cp.async.commit_group;")
template<int N> __device__ __forceinline__ void cp_wait() {
    asm volatile("cp.async.wait_group %0;" :: "n"(N));
}

// quantize one fp32 value: i = round(v*qs) in [-32256,32256]; split base 254
__device__ __forceinline__ void quant1(float v, float qs, int& h, int& l) {
    int i = __float2int_rn(v * qs);
    h = __float2int_rn((float)i * (1.0f / 254.0f));
    l = i - h * 254;
}
__device__ __forceinline__ uint32_t pack4i8(int a, int b, int c, int d) {
    return (uint32_t)(a & 0xff) | ((uint32_t)(b & 0xff) << 8) |
           ((uint32_t)(c & 0xff) << 16) | ((uint32_t)(d & 0xff) << 24);
}

// ---------------- weight quantization: one block per output row ----------------
__global__ void __launch_bounds__(256)
quant_w(const float* __restrict__ src, int8_t* __restrict__ h8, int8_t* __restrict__ l8,
        float* __restrict__ sc, int K)
{
    __shared__ float red[256];
    const int row = blockIdx.x;
    const int tid = threadIdx.x;
    const int nf4 = K >> 2;                      // 192 or 768
    const float4* sp = reinterpret_cast<const float4*>(src + (size_t)row * K);

    float4 v[3];
    float m = 0.f;
#pragma unroll
    for (int c = 0; c < 3; c++) {
        int idx = tid + c * 256;
        if (idx < nf4) {
            v[c] = sp[idx];
            m = fmaxf(m, fmaxf(fmaxf(fabsf(v[c].x), fabsf(v[c].y)),
                               fmaxf(fabsf(v[c].z), fabsf(v[c].w))));
        }
    }
    red[tid] = m;
    __syncthreads();
    for (int st = 128; st > 0; st >>= 1) {
        if (tid < st) red[tid] = fmaxf(red[tid], red[tid + st]);
        __syncthreads();
    }
    const float rmax = red[0];
    const float qs = rmax > 0.f ? QMAX / rmax : 0.f;

    uint32_t* hp = reinterpret_cast<uint32_t*>(h8) + (size_t)row * nf4;
    uint32_t* lp = reinterpret_cast<uint32_t*>(l8) + (size_t)row * nf4;
#pragma unroll
    for (int c = 0; c < 3; c++) {
        int idx = tid + c * 256;
        if (idx < nf4) {
            int h0, l0, h1, l1, h2, l2, h3, l3;
            quant1(v[c].x, qs, h0, l0); quant1(v[c].y, qs, h1, l1);
            quant1(v[c].z, qs, h2, l2); quant1(v[c].w, qs, h3, l3);
            hp[idx] = pack4i8(h0, h1, h2, h3);
            lp[idx] = pack4i8(l0, l1, l2, l3);
        }
    }
    if (tid == 0) sc[row] = rmax;
}

// ---------------- row quantization of fp32 activation matrix (K=3072) ----------------
__global__ void __launch_bounds__(256)
quant_rows(const float* __restrict__ src, int8_t* __restrict__ h8, int8_t* __restrict__ l8,
           float* __restrict__ sc)
{
    __shared__ float red[256];
    const int row = blockIdx.x;
    const int tid = threadIdx.x;
    const int nf4 = MLPDIM >> 2;   // 768
    const float4* sp = reinterpret_cast<const float4*>(src + (size_t)row * MLPDIM);

    float4 v[3];
    float m = 0.f;
#pragma unroll
    for (int c = 0; c < 3; c++) {
        v[c] = sp[tid + c * 256];
        m = fmaxf(m, fmaxf(fmaxf(fabsf(v[c].x), fabsf(v[c].y)),
                           fmaxf(fabsf(v[c].z), fabsf(v[c].w))));
    }
    red[tid] = m;
    __syncthreads();
    for (int st = 128; st > 0; st >>= 1) {
        if (tid < st) red[tid] = fmaxf(red[tid], red[tid + st]);
        __syncthreads();
    }
    const float rmax = red[0];
    const float qs = rmax > 0.f ? QMAX / rmax : 0.f;

    uint32_t* hp = reinterpret_cast<uint32_t*>(h8) + (size_t)row * nf4;
    uint32_t* lp = reinterpret_cast<uint32_t*>(l8) + (size_t)row * nf4;
#pragma unroll
    for (int c = 0; c < 3; c++) {
        int idx = tid + c * 256;
        int h0, l0, h1, l1, h2, l2, h3, l3;
        quant1(v[c].x, qs, h0, l0); quant1(v[c].y, qs, h1, l1);
        quant1(v[c].z, qs, h2, l2); quant1(v[c].w, qs, h3, l3);
        hp[idx] = pack4i8(h0, h1, h2, h3);
        lp[idx] = pack4i8(l0, l1, l2, l3);
    }
    if (tid == 0) sc[row] = rmax;
}

// ---------------- INT8 GEMM (3-term split, cp.async 3-stage) ----------------
// C[n,m] = sA[n]*sW[m]/Q^2 * (254^2*acc0 + 254*acc1) + bias[m] (+epilogue)
// BM=64, BN=64, BK=64 int8 elems. 128 threads = 4 warps (2m x 2n), warp tile 32x32.
// EPI: 0 bias, 1 bias+GELU(exact), 2 bias+residual. All write fp32.
template<int EPI>
__global__ void __launch_bounds__(128, 3)
igemm(const int8_t* __restrict__ Ah, const int8_t* __restrict__ Al,
      const float* __restrict__ asc,
      const int8_t* __restrict__ Wh, const int8_t* __restrict__ Wl,
      const float* __restrict__ wsc,
      const float* __restrict__ bias, const float* __restrict__ res,
      float* __restrict__ C, int Nrows, int K, int M)
{
    constexpr int BM = 64, BN = 64, BK = 64;
    constexpr int ASTB = 80;                  // 64B data + 16B pad
    constexpr int ABYTES = BM * ASTB;         // 5120
    constexpr int BBYTES = BN * ASTB;         // 5120
    constexpr int STAGE = 2 * ABYTES + 2 * BBYTES;  // 20480
    constexpr int O_AH = 0, O_AL = ABYTES, O_BH = 2 * ABYTES, O_BL = 2 * ABYTES + BBYTES;

    extern __shared__ char sm_[];
    const uint32_t sbase = smem_u32(sm_);

    const int tid  = threadIdx.x;
    const int lane = tid & 31;
    const int wid  = tid >> 5;
    const int wm   = wid & 1;
    const int wn   = wid >> 1;
    const int row0 = blockIdx.y * BM;
    const int col0 = blockIdx.x * BN;

    // A staging: 256 16B-units per (hi|lo); 2 per thread
    int asz[2];
    uint32_t adst[2];
    const int8_t *ahs[2], *als[2];
#pragma unroll
    for (int i = 0; i < 2; i++) {
        int u = tid + i * 128;
        int r = u >> 2, q = u & 3;
        asz[i]  = (row0 + r < Nrows) ? 16 : 0;
        adst[i] = (uint32_t)(r * ASTB + q * 16);
        ahs[i]  = Ah + (size_t)(row0 + r) * K + q * 16;
        als[i]  = Al + (size_t)(row0 + r) * K + q * 16;
    }
    // B staging: 256 units; 2 per thread
    uint32_t bdst[2];
    const int8_t *bhs[2], *bls[2];
#pragma unroll
    for (int i = 0; i < 2; i++) {
        int u = tid + i * 128;
        int r = u >> 2, q = u & 3;
        bdst[i] = (uint32_t)(r * ASTB + q * 16);
        bhs[i]  = Wh + (size_t)(col0 + r) * K + q * 16;
        bls[i]  = Wl + (size_t)(col0 + r) * K + q * 16;
    }

    // ldmatrix offsets (byte layout identical to bf16 16816 case)
    uint32_t aoff[2], boff[2];
#pragma unroll
    for (int mi = 0; mi < 2; mi++)
        aoff[mi] = (uint32_t)((wm * 32 + mi * 16 + (lane & 15)) * ASTB + (lane >> 4) * 16);
#pragma unroll
    for (int nj2 = 0; nj2 < 2; nj2++)
        boff[nj2] = (uint32_t)((wn * 32 + nj2 * 16 + (lane & 7) + ((lane >> 4) << 3)) * ASTB
                               + ((lane >> 3) & 1) * 16);

    int acc0[2][4][4], acc1[2][4][4];
#pragma unroll
    for (int mi = 0; mi < 2; mi++)
#pragma unroll
        for (int nj = 0; nj < 4; nj++)
#pragma unroll
            for (int v = 0; v < 4; v++) { acc0[mi][nj][v] = 0; acc1[mi][nj][v] = 0; }

    const int KT = K / BK;

    auto load_stage = [&](int s, int k0) {
        const uint32_t sb = sbase + (uint32_t)(s * STAGE);
#pragma unroll
        for (int i = 0; i < 2; i++) {
            CP16(sb + O_AH + adst[i], ahs[i] + k0, asz[i]);
            CP16(sb + O_AL + adst[i], als[i] + k0, asz[i]);
            CP16(sb + O_BH + bdst[i], bhs[i] + k0, 16);
            CP16(sb + O_BL + bdst[i], bls[i] + k0, 16);
        }
    };

    load_stage(0, 0);  CP_COMMIT();
    load_stage(1, BK); CP_COMMIT();

    for (int kt = 0; kt < KT; kt++) {
        cp_wait<1>();
        __syncthreads();
        if (kt + 2 < KT) load_stage((kt + 2) % 3, (kt + 2) * BK);
        CP_COMMIT();

        const uint32_t sb = sbase + (uint32_t)((kt % 3) * STAGE);
#pragma unroll
        for (int sub = 0; sub < 2; sub++) {
            const uint32_t kb = (uint32_t)(sub * 32);
            uint32_t ah[2][4], al[2][4], bh[2][4], bl[2][4];
#pragma unroll
            for (int mi = 0; mi < 2; mi++)
                ldmx4(ah[mi][0], ah[mi][1], ah[mi][2], ah[mi][3], sb + O_AH + aoff[mi] + kb);
#pragma unroll
            for (int nj2 = 0; nj2 < 2; nj2++)
                ldmx4(bh[nj2][0], bh[nj2][1], bh[nj2][2], bh[nj2][3], sb + O_BH + boff[nj2] + kb);
            // acc0 += ah*bh
#pragma unroll
            for (int mi = 0; mi < 2; mi++)
#pragma unroll
                for (int nj = 0; nj < 4; nj++)
                    imma16832(acc0[mi][nj], ah[mi],
                              bh[nj >> 1][(nj & 1) * 2], bh[nj >> 1][(nj & 1) * 2 + 1]);
            // acc1 += ah*bl
#pragma unroll
            for (int nj2 = 0; nj2 < 2; nj2++)
                ldmx4(bl[nj2][0], bl[nj2][1], bl[nj2][2], bl[nj2][3], sb + O_BL + boff[nj2] + kb);
#pragma unroll
            for (int mi = 0; mi < 2; mi++)
#pragma unroll
                for (int nj = 0; nj < 4; nj++)
                    imma16832(acc1[mi][nj], ah[mi],
                              bl[nj >> 1][(nj & 1) * 2], bl[nj >> 1][(nj & 1) * 2 + 1]);
            // acc1 += al*bh
#pragma unroll
            for (int mi = 0; mi < 2; mi++)
                ldmx4(al[mi][0], al[mi][1], al[mi][2], al[mi][3], sb + O_AL + aoff[mi] + kb);
#pragma unroll
            for (int mi = 0; mi < 2; mi++)
#pragma unroll
                for (int nj = 0; nj < 4; nj++)
                    imma16832(acc1[mi][nj], al[mi],
                              bh[nj >> 1][(nj & 1) * 2], bh[nj >> 1][(nj & 1) * 2 + 1]);
        }
    }

    // ---- epilogue ----
    const int g  = lane >> 2;
    const int tg = lane & 3;
#pragma unroll
    for (int mi = 0; mi < 2; mi++) {
#pragma unroll
        for (int half = 0; half < 2; half++) {
            const int r = row0 + wm * 32 + mi * 16 + g + half * 8;
            if (r >= Nrows) continue;
            const float rowf = asc[r] * INVQ2;
#pragma unroll
            for (int nj = 0; nj < 4; nj++) {
                const int c = col0 + wn * 32 + nj * 8 + tg * 2;
                const float f0 = rowf * wsc[c];
                const float f1 = rowf * wsc[c + 1];
                float v0 = ((float)acc0[mi][nj][half * 2 + 0] * 64516.0f
                          + (float)acc1[mi][nj][half * 2 + 0] * 254.0f) * f0 + bias[c];
                float v1 = ((float)acc0[mi][nj][half * 2 + 1] * 64516.0f
                          + (float)acc1[mi][nj][half * 2 + 1] * 254.0f) * f1 + bias[c + 1];
                if (EPI == 1) {
                    v0 = 0.5f * v0 * (1.0f + erff(v0 * 0.7071067811865475f));
                    v1 = 0.5f * v1 * (1.0f + erff(v1 * 0.7071067811865475f));
                } else if (EPI == 2) {
                    v0 += res[(size_t)r * M + c];
                    v1 += res[(size_t)r * M + c + 1];
                }
                C[(size_t)r * M + c]     = v0;
                C[(size_t)r * M + c + 1] = v1;
            }
        }
    }
}

// ---------------- LayerNorm -> int8 hi/lo + scale ----------------
__global__ void __launch_bounds__(256)
ln_kernel(const float* __restrict__ x, const float* __restrict__ s,
          const float* __restrict__ b, int8_t* __restrict__ yh,
          int8_t* __restrict__ yl, float* __restrict__ ysc)
{
    const int row = blockIdx.x;
    const int tid = threadIdx.x;
    const float* xr = x + (size_t)row * DIM;

    float v0 = xr[tid];
    float v1 = xr[tid + 256];
    float v2 = xr[tid + 512];

    __shared__ float ssum[256], ssq[256];
    ssum[tid] = v0 + v1 + v2;
    ssq[tid]  = v0 * v0 + v1 * v1 + v2 * v2;
    __syncthreads();
    for (int st = 128; st > 0; st >>= 1) {
        if (tid < st) { ssum[tid] += ssum[tid + st]; ssq[tid] += ssq[tid + st]; }
        __syncthreads();
    }
    const float mean = ssum[0] * (1.0f / DIM);
    const float var  = ssq[0] * (1.0f / DIM) - mean * mean;
    const float inv  = rsqrtf(var + 1e-5f);

    float y0 = (v0 - mean) * inv * s[tid]       + b[tid];
    float y1 = (v1 - mean) * inv * s[tid + 256] + b[tid + 256];
    float y2 = (v2 - mean) * inv * s[tid + 512] + b[tid + 512];

    __syncthreads();   // done reading ssum[0]/ssq[0]
    ssum[tid] = fmaxf(fabsf(y0), fmaxf(fabsf(y1), fabsf(y2)));
    __syncthreads();
    for (int st = 128; st > 0; st >>= 1) {
        if (tid < st) ssum[tid] = fmaxf(ssum[tid], ssum[tid + st]);
        __syncthreads();
    }
    const float rmax = ssum[0];
    const float qs = rmax > 0.f ? QMAX / rmax : 0.f;

    size_t o = (size_t)row * DIM;
    int h, l;
    quant1(y0, qs, h, l); yh[o + tid]       = (int8_t)h; yl[o + tid]       = (int8_t)l;
    quant1(y1, qs, h, l); yh[o + tid + 256] = (int8_t)h; yl[o + tid + 256] = (int8_t)l;
    quant1(y2, qs, h, l); yh[o + tid + 512] = (int8_t)h; yl[o + tid + 512] = (int8_t)l;
    if (tid == 0) ysc[row] = rmax;
}

// ---------------- Attention: block per (b,s), warp per head -> int8 out ----------------
__global__ void __launch_bounds__(384)
attn_kernel(const float* __restrict__ qkv, const int* __restrict__ routes,
            int8_t* __restrict__ outh, int8_t* __restrict__ outl, float* __restrict__ osc)
{
    __shared__ int   sidx[200];
    __shared__ float sc[NHEAD][200];
    __shared__ float qs[NHEAD][HDIM];
    __shared__ float obuf[DIM];
    __shared__ float rmax[NHEAD];

    const int b    = blockIdx.x / SEQ;
    const int s    = blockIdx.x % SEQ;
    const int tid  = threadIdx.x;
    const int h    = tid >> 5;     // warp = head
    const int lane = tid & 31;

    const int nk = (s == 0) ? SEQ : TOPK;
    for (int j = tid; j < nk; j += 384)
        sidx[j] = (s == 0) ? j : (routes[(s - 1) * TOPK + j] + 1);

    const float* base = qkv + (size_t)b * SEQ * (3 * DIM);
    const float* qp = base + (size_t)s * (3 * DIM) + h * HDIM;
    qs[h][lane]      = qp[lane];
    qs[h][lane + 32] = qp[lane + 32];
    __syncthreads();

    for (int j = lane; j < nk; j += 32) {
        const float* kp = base + (size_t)sidx[j] * (3 * DIM) + DIM + h * HDIM;
        float acc = 0.f;
#pragma unroll
        for (int d = 0; d < HDIM; d++) acc = fmaf(qs[h][d], kp[d], acc);
        sc[h][j] = acc * ATT_SCALE;
    }
    __syncwarp();

    float m = -1e30f;
    for (int j = lane; j < nk; j += 32) m = fmaxf(m, sc[h][j]);
#pragma unroll
    for (int o = 16; o; o >>= 1) m = fmaxf(m, __shfl_xor_sync(0xffffffffu, m, o));

    float sum = 0.f;
    for (int j = lane; j < nk; j += 32) {
        float e = expf(sc[h][j] - m);
        sc[h][j] = e;
        sum += e;
    }
#pragma unroll
    for (int o = 16; o; o >>= 1) sum += __shfl_xor_sync(0xffffffffu, sum, o);
    __syncwarp();
    const float inv = 1.f / sum;

    float o0 = 0.f, o1 = 0.f;
    for (int j = 0; j < nk; j++) {
        float p = sc[h][j];
        const float* vp = base + (size_t)sidx[j] * (3 * DIM) + 2 * DIM + h * HDIM;
        o0 = fmaf(p, vp[2 * lane],     o0);
        o1 = fmaf(p, vp[2 * lane + 1], o1);
    }
    obuf[h * HDIM + 2 * lane]     = o0 * inv;
    obuf[h * HDIM + 2 * lane + 1] = o1 * inv;
    __syncthreads();

    // block max over 768 values (2 per thread)
    float mm = fmaxf(fabsf(obuf[tid]), fabsf(obuf[tid + 384]));
#pragma unroll
    for (int o = 16; o; o >>= 1) mm = fmaxf(mm, __shfl_xor_sync(0xffffffffu, mm, o));
    if (lane == 0) rmax[h] = mm;
    __syncthreads();
    if (tid == 0) {
        float t = rmax[0];
#pragma unroll
        for (int i = 1; i < NHEAD; i++) t = fmaxf(t, rmax[i]);
        rmax[0] = t;
    }
    __syncthreads();

    const float rm = rmax[0];
    const float qsc = rm > 0.f ? QMAX / rm : 0.f;
    const size_t ob = (size_t)blockIdx.x * DIM;
    int hh, ll;
    quant1(obuf[tid], qsc, hh, ll);
    outh[ob + tid] = (int8_t)hh; outl[ob + tid] = (int8_t)ll;
    quant1(obuf[tid + 384], qsc, hh, ll);
    outh[ob + tid + 384] = (int8_t)hh; outl[ob + tid + 384] = (int8_t)ll;
    if (tid == 0) osc[blockIdx.x] = rm;
}

// ---------------- Patchify -> int8 hi/lo + scale (block per patch row) ----------------
__global__ void __launch_bounds__(256)
patchify_kernel(const float* __restrict__ x, int8_t* __restrict__ xph,
                int8_t* __restrict__ xpl, float* __restrict__ xsc)
{
    __shared__ float red[256];
    const int bp  = blockIdx.x;           // 0..NROWS_P-1
    const int tid = threadIdx.x;
    const int p   = bp % NPATCH;
    const int b   = bp / NPATCH;
    const int gy  = p / GRID, gx = p % GRID;

    float v[3];
    float m = 0.f;
#pragma unroll
    for (int i = 0; i < 3; i++) {
        int e = tid + i * 256;
        int c = e / (PATCH * PATCH);
        int r = e % (PATCH * PATCH);
        int py = r / PATCH, px = r % PATCH;
        v[i] = x[(((size_t)b * CHN + c) * IMG + gy * PATCH + py) * IMG + gx * PATCH + px];
        m = fmaxf(m, fabsf(v[i]));
    }
    red[tid] = m;
    __syncthreads();
    for (int st = 128; st > 0; st >>= 1) {
        if (tid < st) red[tid] = fmaxf(red[tid], red[tid + st]);
        __syncthreads();
    }
    const float rmax = red[0];
    const float qs = rmax > 0.f ? QMAX / rmax : 0.f;

    size_t o = (size_t)bp * DIM;
    int h, l;
#pragma unroll
    for (int i = 0; i < 3; i++) {
        quant1(v[i], qs, h, l);
        xph[o + tid + i * 256] = (int8_t)h;
        xpl[o + tid + i * 256] = (int8_t)l;
    }
    if (tid == 0) xsc[bp] = rmax;
}

// ---------------- Assemble ----------------
__global__ void assemble_kernel(const float* __restrict__ tok, const float* __restrict__ cls,
                                const float* __restrict__ pos, float* __restrict__ hout)
{
    int idx = blockIdx.x * blockDim.x + threadIdx.x;
    const int total = NROWS * DIM;
    if (idx >= total) return;
    int d  = idx % DIM;
    int bs = idx / DIM;
    int s  = bs % SEQ;
    int b  = bs / SEQ;
    float v = (s == 0) ? cls[d] : tok[((size_t)b * NPATCH + (s - 1)) * DIM + d];
    hout[idx] = v + pos[(size_t)s * DIM + d];
}

// ---------------- host launcher ----------------
extern "C" void kernel_launch(void* const* d_in, const int* in_sizes, int n_in,
                              void* d_out, int out_size)
{
    const float* x        = (const float*)d_in[0];
    const float* patch_w  = (const float*)d_in[1];
    const float* patch_b  = (const float*)d_in[2];
    const float* cls_tok  = (const float*)d_in[3];
    const float* pos_emb  = (const float*)d_in[4];
    const float* qkv_w    = (const float*)d_in[5];
    const float* qkv_b    = (const float*)d_in[6];
    const float* proj_w   = (const float*)d_in[7];
    const float* proj_b   = (const float*)d_in[8];
    const float* ln1_s    = (const float*)d_in[9];
    const float* ln1_b    = (const float*)d_in[10];
    const float* ln2_s    = (const float*)d_in[11];
    const float* ln2_b    = (const float*)d_in[12];
    const float* fc1_w    = (const float*)d_in[13];
    const float* fc1_b    = (const float*)d_in[14];
    const float* fc2_w    = (const float*)d_in[15];
    const float* fc2_b    = (const float*)d_in[16];
    const int*   routes   = (const int*)d_in[17];

    float *hbuf, *qkv, *mlp;
    int8_t *xnh, *xnl, *ath, *atl, *mlh, *mll, *wh, *wl;
    float *xnsc, *atsc, *mlsc, *wsc;
    cudaGetSymbolAddress((void**)&hbuf, g_h);
    cudaGetSymbolAddress((void**)&qkv,  g_qkv);
    cudaGetSymbolAddress((void**)&mlp,  g_mlp);
    cudaGetSymbolAddress((void**)&xnh,  g_xnh8);
    cudaGetSymbolAddress((void**)&xnl,  g_xnl8);
    cudaGetSymbolAddress((void**)&xnsc, g_xnsc);
    cudaGetSymbolAddress((void**)&ath,  g_ath8);
    cudaGetSymbolAddress((void**)&atl,  g_atl8);
    cudaGetSymbolAddress((void**)&atsc, g_atsc);
    cudaGetSymbolAddress((void**)&mlh,  g_mlh8);
    cudaGetSymbolAddress((void**)&mll,  g_mll8);
    cudaGetSymbolAddress((void**)&mlsc, g_mlsc);
    cudaGetSymbolAddress((void**)&wh,   g_wh8);
    cudaGetSymbolAddress((void**)&wl,   g_wl8);
    cudaGetSymbolAddress((void**)&wsc,  g_wsc);

    const int SMEM = 3 * 20480;   // 61440
    cudaFuncSetAttribute(igemm<0>, cudaFuncAttributeMaxDynamicSharedMemorySize, SMEM);
    cudaFuncSetAttribute(igemm<1>, cudaFuncAttributeMaxDynamicSharedMemorySize, SMEM);
    cudaFuncSetAttribute(igemm<2>, cudaFuncAttributeMaxDynamicSharedMemorySize, SMEM);

    // ---- weight quantization (per output row) ----
    quant_w<<<DIM, 256>>>(patch_w, wh + OFF_PATCH, wl + OFF_PATCH, wsc + WS_PATCH, DIM);
    quant_w<<<NLAYER * 3 * DIM, 256>>>(qkv_w, wh + OFF_QKV, wl + OFF_QKV, wsc + WS_QKV, DIM);
    quant_w<<<NLAYER * DIM, 256>>>(proj_w, wh + OFF_PROJ, wl + OFF_PROJ, wsc + WS_PROJ, DIM);
    quant_w<<<NLAYER * MLPDIM, 256>>>(fc1_w, wh + OFF_FC1, wl + OFF_FC1, wsc + WS_FC1, DIM);
    quant_w<<<NLAYER * DIM, 256>>>(fc2_w, wh + OFF_FC2, wl + OFF_FC2, wsc + WS_FC2, MLPDIM);

    const int rt = (NROWS + 63) / 64;      // 25
    const int rtp = (NROWS_P + 63) / 64;   // 25

    // patch embed: patchify->int8 (mlh/mll/mlsc), GEMM->qkv fp32, assemble->h
    patchify_kernel<<<NROWS_P, 256>>>(x, mlh, mll, mlsc);
    igemm<0><<<dim3(DIM / 64, rtp), 128, SMEM>>>(
        mlh, mll, mlsc, wh + OFF_PATCH, wl + OFF_PATCH, wsc + WS_PATCH,
        patch_b, nullptr, qkv, NROWS_P, DIM, DIM);
    assemble_kernel<<<(NROWS * DIM + 255) / 256, 256>>>(qkv, cls_tok, pos_emb, hbuf);

    for (int l = 0; l < NLAYER; l++) {
        const size_t oq  = OFF_QKV  + (size_t)l * 3 * DIM * DIM;
        const size_t op  = OFF_PROJ + (size_t)l * DIM * DIM;
        const size_t of1 = OFF_FC1  + (size_t)l * MLPDIM * DIM;
        const size_t of2 = OFF_FC2  + (size_t)l * DIM * MLPDIM;
        const size_t sq  = WS_QKV  + (size_t)l * 3 * DIM;
        const size_t sp  = WS_PROJ + (size_t)l * DIM;
        const size_t sf1 = WS_FC1  + (size_t)l * MLPDIM;
        const size_t sf2 = WS_FC2  + (size_t)l * DIM;
        const float* qb  = qkv_b  + (size_t)l * 3 * DIM;
        const float* pb  = proj_b + (size_t)l * DIM;
        const float* f1b = fc1_b  + (size_t)l * MLPDIM;
        const float* f2b = fc2_b  + (size_t)l * DIM;

        ln_kernel<<<NROWS, 256>>>(hbuf, ln1_s + (size_t)l * DIM, ln1_b + (size_t)l * DIM,
                                  xnh, xnl, xnsc);
        igemm<0><<<dim3(3 * DIM / 64, rt), 128, SMEM>>>(
            xnh, xnl, xnsc, wh + oq, wl + oq, wsc + sq,
            qb, nullptr, qkv, NROWS, DIM, 3 * DIM);
        attn_kernel<<<NROWS, 384>>>(qkv, routes, ath, atl, atsc);
        igemm<2><<<dim3(DIM / 64, rt), 128, SMEM>>>(
            ath, atl, atsc, wh + op, wl + op, wsc + sp,
            pb, hbuf, hbuf, NROWS, DIM, DIM);
        ln_kernel<<<NROWS, 256>>>(hbuf, ln2_s + (size_t)l * DIM, ln2_b + (size_t)l * DIM,
                                  xnh, xnl, xnsc);
        igemm<1><<<dim3(MLPDIM / 64, rt), 128, SMEM>>>(
            xnh, xnl, xnsc, wh + of1, wl + of1, wsc + sf1,
            f1b, nullptr, mlp, NROWS, DIM, MLPDIM);
        quant_rows<<<NROWS, 256>>>(mlp, mlh, mll, mlsc);
        float* outp = (l == NLAYER - 1) ? (float*)d_out : hbuf;
        igemm<2><<<dim3(DIM / 64, rt), 128, SMEM>>>(
            mlh, mll, mlsc, wh + of2, wl + of2, wsc + sf2,
            f2b, hbuf, outp, NROWS, MLPDIM, DIM);
    }
}

// round 7
// speedup vs baseline: 1.7029x; 1.7029x over previous
#include <cuda_runtime.h>
#include <cuda_bf16.h>
#include <math.h>
#include <stdint.h>

// ---------------- problem constants ----------------
#define BATCH 8
#define CHN 3
#define IMG 224
#define PATCH 16
#define GRID 14
#define NPATCH 196
#define SEQ 197
#define DIM 768
#define NHEAD 12
#define HDIM 64
#define NLAYER 12
#define TOPK 32
#define MLPDIM 3072
#define ATT_SCALE 0.125f

#define NROWS (BATCH*SEQ)           // 1576
#define NROWS_P (BATCH*NPATCH)      // 1568

#define NW_PATCH (DIM*DIM)
#define NW_QKV   (NLAYER*3*DIM*DIM)
#define NW_PROJ  (NLAYER*DIM*DIM)
#define NW_FC1   (NLAYER*MLPDIM*DIM)
#define NW_FC2   (NLAYER*DIM*MLPDIM)
#define OFF_PATCH 0
#define OFF_QKV   (OFF_PATCH + NW_PATCH)
#define OFF_PROJ  (OFF_QKV + NW_QKV)
#define OFF_FC1   (OFF_PROJ + NW_PROJ)
#define OFF_FC2   (OFF_FC1 + NW_FC1)
#define NW_TOTAL  (OFF_FC2 + NW_FC2)

// ---------------- scratch ----------------
__device__ float g_h  [BATCH*SEQ*DIM];
__device__ float g_qkv[BATCH*SEQ*3*DIM];
__device__ __nv_bfloat16 g_xnh [BATCH*SEQ*DIM];
__device__ __nv_bfloat16 g_xnl [BATCH*SEQ*DIM];
__device__ __nv_bfloat16 g_atth[BATCH*SEQ*DIM];
__device__ __nv_bfloat16 g_attl[BATCH*SEQ*DIM];
__device__ __nv_bfloat16 g_mlph[BATCH*SEQ*MLPDIM];
__device__ __nv_bfloat16 g_mlpl[BATCH*SEQ*MLPDIM];
__device__ __nv_bfloat16 g_wh[NW_TOTAL];
__device__ __nv_bfloat16 g_wl[NW_TOTAL];

// ---------------- helpers ----------------
__device__ __forceinline__ uint32_t smem_u32(const void* p) {
    uint32_t a;
    asm("{ .reg .u64 t; cvta.to.shared.u64 t, %1; cvt.u32.u64 %0, t; }" : "=r"(a) : "l"(p));
    return a;
}
__device__ __forceinline__ uint32_t pack_bf16(__nv_bfloat16 a, __nv_bfloat16 b) {
    return (uint32_t)__bfloat16_as_ushort(a) | ((uint32_t)__bfloat16_as_ushort(b) << 16);
}
__device__ __forceinline__ void split1(float v, __nv_bfloat16& h, __nv_bfloat16& l) {
    h = __float2bfloat16(v);
    l = __float2bfloat16(v - __bfloat162float(h));
}
__device__ __forceinline__ void ldmx4(uint32_t& r0, uint32_t& r1, uint32_t& r2, uint32_t& r3,
                                      uint32_t addr) {
    asm volatile("ldmatrix.sync.aligned.m8n8.x4.shared.b16 {%0,%1,%2,%3}, [%4];"
                 : "=r"(r0), "=r"(r1), "=r"(r2), "=r"(r3) : "r"(addr));
}
__device__ __forceinline__ void mma16816(float* d, const uint32_t* a, uint32_t b0, uint32_t b1) {
    asm volatile(
        "mma.sync.aligned.m16n8k16.row.col.f32.bf16.bf16.f32 "
        "{%0,%1,%2,%3},{%4,%5,%6,%7},{%8,%9},{%0,%1,%2,%3};"
        : "+f"(d[0]), "+f"(d[1]), "+f"(d[2]), "+f"(d[3])
        : "r"(a[0]), "r"(a[1]), "r"(a[2]), "r"(a[3]), "r"(b0), "r"(b1));
}
#define CP16(dst, src, sz) \
    asm volatile("cp.async.cg.shared.global [%0], [%1], 16, %2;" \
                 :: "r"(dst), "l"(src), "r"(sz))
#define CP_COMMIT() asm volatile("cp.async.commit_group;")
template<int N> __device__ __forceinline__ void cp_wait() {
    asm volatile("cp.async.wait_group %0;" :: "n"(N));
}

// ---------------- weight pre-conversion ----------------
__global__ void __launch_bounds__(256)
cvt_weights(const float* __restrict__ src, __nv_bfloat16* __restrict__ hi,
            __nv_bfloat16* __restrict__ lo, int n4)
{
    int i = blockIdx.x * blockDim.x + threadIdx.x;
    if (i >= n4) return;
    float4 f = reinterpret_cast<const float4*>(src)[i];
    __nv_bfloat16 h0, h1, h2, h3, l0, l1, l2, l3;
    split1(f.x, h0, l0); split1(f.y, h1, l1);
    split1(f.z, h2, l2); split1(f.w, h3, l3);
    uint2 H, L;
    H.x = pack_bf16(h0, h1); H.y = pack_bf16(h2, h3);
    L.x = pack_bf16(l0, l1); L.y = pack_bf16(l2, l3);
    reinterpret_cast<uint2*>(hi)[i] = H;
    reinterpret_cast<uint2*>(lo)[i] = L;
}

// ---------------- HMMA GEMM (bf16x3, cp.async 2-stage, warp tile 32x64) ----------------
// C[n,m] = sum_k A[n,k]*W[m,k] + bias[m] (+epilogue)
// BN=128, BK=32. BM=128 -> 256 thr (8 warps, 4m x 2n), 2 CTAs/SM.
//                BM=64  -> 128 thr (4 warps, 2m x 2n), 3 CTAs/SM.
// EPI: 0 bias->fp32, 1 bias+GELU->bf16 hi/lo, 2 bias+residual->fp32
template<int BM, int EPI, int OCC>
__global__ void __launch_bounds__(BM*2, OCC)
hgemm(const __nv_bfloat16* __restrict__ Ah, const __nv_bfloat16* __restrict__ Al,
      const __nv_bfloat16* __restrict__ Wh, const __nv_bfloat16* __restrict__ Wl,
      const float* __restrict__ bias, const float* __restrict__ res,
      float* __restrict__ C, __nv_bfloat16* __restrict__ Ch, __nv_bfloat16* __restrict__ Cl,
      int Nrows, int K, int M)
{
    constexpr int BN = 128, BK = 32;
    constexpr int THREADS = BM * 2;
    constexpr int MW = BM / 32;
    constexpr int ASTB = 80;                // 64B data + 16B pad -> conflict-free
    constexpr int ABYTES = BM * ASTB;
    constexpr int BBYTES = BN * ASTB;
    constexpr int STAGE = 2 * ABYTES + 2 * BBYTES;
    constexpr int O_AH = 0, O_AL = ABYTES, O_BH = 2 * ABYTES, O_BL = 2 * ABYTES + BBYTES;

    extern __shared__ char sm_[];
    const uint32_t sbase = smem_u32(sm_);

    const int tid  = threadIdx.x;
    const int lane = tid & 31;
    const int wid  = tid >> 5;
    const int wm   = wid % MW;
    const int wn   = wid / MW;
    const int row0 = blockIdx.y * BM;
    const int col0 = blockIdx.x * BN;

    // A staging: BM*4 16B-units, 2 per thread
    int asz[2];
    uint32_t adst[2];
    const __nv_bfloat16 *ahs[2], *als[2];
#pragma unroll
    for (int i = 0; i < 2; i++) {
        int u = tid + i * THREADS;
        int r = u >> 2, q = u & 3;
        asz[i]  = (row0 + r < Nrows) ? 16 : 0;
        adst[i] = (uint32_t)(r * ASTB + q * 16);
        ahs[i]  = Ah + (size_t)(row0 + r) * K + q * 8;
        als[i]  = Al + (size_t)(row0 + r) * K + q * 8;
    }
    // B staging: 512 16B-units
    constexpr int BU = 512 / THREADS;
    uint32_t bdst[BU];
    const __nv_bfloat16 *bhs[BU], *bls[BU];
#pragma unroll
    for (int i = 0; i < BU; i++) {
        int u = tid + i * THREADS;
        int r = u >> 2, q = u & 3;
        bdst[i] = (uint32_t)(r * ASTB + q * 16);
        bhs[i]  = Wh + (size_t)(col0 + r) * K + q * 8;
        bls[i]  = Wl + (size_t)(col0 + r) * K + q * 8;
    }

    // ldmatrix offsets within a stage
    uint32_t aoff[2], boff[4];
#pragma unroll
    for (int mi = 0; mi < 2; mi++)
        aoff[mi] = (uint32_t)((wm * 32 + mi * 16 + (lane & 15)) * ASTB + (lane >> 4) * 16);
#pragma unroll
    for (int nj2 = 0; nj2 < 4; nj2++)
        boff[nj2] = (uint32_t)((wn * 64 + nj2 * 16 + (lane & 7) + ((lane >> 4) << 3)) * ASTB
                               + ((lane >> 3) & 1) * 16);

    float acc[2][8][4];
#pragma unroll
    for (int mi = 0; mi < 2; mi++)
#pragma unroll
        for (int nj = 0; nj < 8; nj++)
#pragma unroll
            for (int v = 0; v < 4; v++) acc[mi][nj][v] = 0.f;

    const int KT = K / BK;

    auto load_stage = [&](int s, int k0) {
        const uint32_t sb = sbase + (uint32_t)(s * STAGE);
#pragma unroll
        for (int i = 0; i < 2; i++) {
            CP16(sb + O_AH + adst[i], ahs[i] + k0, asz[i]);
            CP16(sb + O_AL + adst[i], als[i] + k0, asz[i]);
        }
#pragma unroll
        for (int i = 0; i < BU; i++) {
            CP16(sb + O_BH + bdst[i], bhs[i] + k0, 16);
            CP16(sb + O_BL + bdst[i], bls[i] + k0, 16);
        }
    };

    load_stage(0, 0);
    CP_COMMIT();

    for (int kt = 0; kt < KT; kt++) {
        cp_wait<0>();          // stage kt resident
        __syncthreads();       // all warps done computing stage kt-1 (same slot as kt+1)
        if (kt + 1 < KT) {
            load_stage((kt + 1) & 1, (kt + 1) * BK);   // overlaps with compute below
            CP_COMMIT();
        }

        const uint32_t sb = sbase + (uint32_t)((kt & 1) * STAGE);
#pragma unroll
        for (int k16 = 0; k16 < 2; k16++) {
            const uint32_t kb = (uint32_t)(k16 * 32);
            uint32_t ah[2][4], al[2][4], bh[4][4], bl[4][4];
#pragma unroll
            for (int mi = 0; mi < 2; mi++)
                ldmx4(ah[mi][0], ah[mi][1], ah[mi][2], ah[mi][3], sb + O_AH + aoff[mi] + kb);
#pragma unroll
            for (int nj2 = 0; nj2 < 4; nj2++)
                ldmx4(bh[nj2][0], bh[nj2][1], bh[nj2][2], bh[nj2][3], sb + O_BH + boff[nj2] + kb);
            // hi*hi
#pragma unroll
            for (int mi = 0; mi < 2; mi++)
#pragma unroll
                for (int nj = 0; nj < 8; nj++)
                    mma16816(acc[mi][nj], ah[mi],
                             bh[nj >> 1][(nj & 1) * 2], bh[nj >> 1][(nj & 1) * 2 + 1]);
            // hi*lo
#pragma unroll
            for (int nj2 = 0; nj2 < 4; nj2++)
                ldmx4(bl[nj2][0], bl[nj2][1], bl[nj2][2], bl[nj2][3], sb + O_BL + boff[nj2] + kb);
#pragma unroll
            for (int mi = 0; mi < 2; mi++)
#pragma unroll
                for (int nj = 0; nj < 8; nj++)
                    mma16816(acc[mi][nj], ah[mi],
                             bl[nj >> 1][(nj & 1) * 2], bl[nj >> 1][(nj & 1) * 2 + 1]);
            // lo*hi
#pragma unroll
            for (int mi = 0; mi < 2; mi++)
                ldmx4(al[mi][0], al[mi][1], al[mi][2], al[mi][3], sb + O_AL + aoff[mi] + kb);
#pragma unroll
            for (int mi = 0; mi < 2; mi++)
#pragma unroll
                for (int nj = 0; nj < 8; nj++)
                    mma16816(acc[mi][nj], al[mi],
                             bh[nj >> 1][(nj & 1) * 2], bh[nj >> 1][(nj & 1) * 2 + 1]);
        }
    }

    // ---- epilogue ----
    const int g  = lane >> 2;
    const int tg = lane & 3;
#pragma unroll
    for (int mi = 0; mi < 2; mi++) {
#pragma unroll
        for (int half = 0; half < 2; half++) {
            const int r = row0 + wm * 32 + mi * 16 + g + half * 8;
            if (r >= Nrows) continue;
#pragma unroll
            for (int nj = 0; nj < 8; nj++) {
                const int c = col0 + wn * 64 + nj * 8 + tg * 2;
                float v0 = acc[mi][nj][half * 2 + 0] + bias[c];
                float v1 = acc[mi][nj][half * 2 + 1] + bias[c + 1];
                if (EPI == 1) {
                    v0 = 0.5f * v0 * (1.0f + erff(v0 * 0.7071067811865475f));
                    v1 = 0.5f * v1 * (1.0f + erff(v1 * 0.7071067811865475f));
                    __nv_bfloat16 h0, l0, h1, l1;
                    split1(v0, h0, l0); split1(v1, h1, l1);
                    *reinterpret_cast<uint32_t*>(Ch + (size_t)r * M + c) = pack_bf16(h0, h1);
                    *reinterpret_cast<uint32_t*>(Cl + (size_t)r * M + c) = pack_bf16(l0, l1);
                } else {
                    if (EPI == 2) {
                        v0 += res[(size_t)r * M + c];
                        v1 += res[(size_t)r * M + c + 1];
                    }
                    C[(size_t)r * M + c]     = v0;
                    C[(size_t)r * M + c + 1] = v1;
                }
            }
        }
    }
}

// ---------------- LayerNorm -> bf16 hi/lo ----------------
__global__ void __launch_bounds__(256)
ln_kernel(const float* __restrict__ x, const float* __restrict__ s,
          const float* __restrict__ b, __nv_bfloat16* __restrict__ yh,
          __nv_bfloat16* __restrict__ yl)
{
    const int row = blockIdx.x;
    const int tid = threadIdx.x;
    const float* xr = x + (size_t)row * DIM;

    float v0 = xr[tid];
    float v1 = xr[tid + 256];
    float v2 = xr[tid + 512];

    __shared__ float ssum[256], ssq[256];
    ssum[tid] = v0 + v1 + v2;
    ssq[tid]  = v0 * v0 + v1 * v1 + v2 * v2;
    __syncthreads();
    for (int st = 128; st > 0; st >>= 1) {
        if (tid < st) { ssum[tid] += ssum[tid + st]; ssq[tid] += ssq[tid + st]; }
        __syncthreads();
    }
    const float mean = ssum[0] * (1.0f / DIM);
    const float var  = ssq[0] * (1.0f / DIM) - mean * mean;
    const float inv  = rsqrtf(var + 1e-5f);

    __nv_bfloat16 h, l;
    size_t o = (size_t)row * DIM;
    float y0 = (v0 - mean) * inv * s[tid]       + b[tid];
    float y1 = (v1 - mean) * inv * s[tid + 256] + b[tid + 256];
    float y2 = (v2 - mean) * inv * s[tid + 512] + b[tid + 512];
    split1(y0, h, l); yh[o + tid]       = h; yl[o + tid]       = l;
    split1(y1, h, l); yh[o + tid + 256] = h; yl[o + tid + 256] = l;
    split1(y2, h, l); yh[o + tid + 512] = h; yl[o + tid + 512] = l;
}

// ---------------- Attention -> bf16 hi/lo ----------------
__global__ void __launch_bounds__(128)
attn_kernel(const float* __restrict__ qkv, const int* __restrict__ routes,
            __nv_bfloat16* __restrict__ outh, __nv_bfloat16* __restrict__ outl)
{
    __shared__ float sc[4][200];
    __shared__ int   sidx[4][200];
    __shared__ float qs[4][64];

    const int bh   = blockIdx.x;
    const int b    = bh / NHEAD;
    const int h    = bh % NHEAD;
    const int warp = threadIdx.x >> 5;
    const int lane = threadIdx.x & 31;
    const int s    = blockIdx.y * 4 + warp;
    if (s >= SEQ) return;

    const float* base = qkv + (size_t)b * SEQ * (3 * DIM);
    const float* qp = base + (size_t)s * (3 * DIM) + h * HDIM;
    qs[warp][lane]      = qp[lane];
    qs[warp][lane + 32] = qp[lane + 32];
    __syncwarp();

    const int nk = (s == 0) ? SEQ : TOPK;

    for (int j = lane; j < nk; j += 32) {
        int kidx = (s == 0) ? j : (routes[(s - 1) * TOPK + j] + 1);
        const float* kp = base + (size_t)kidx * (3 * DIM) + DIM + h * HDIM;
        float acc = 0.f;
#pragma unroll
        for (int d = 0; d < HDIM; d++) acc = fmaf(qs[warp][d], kp[d], acc);
        sc[warp][j]   = acc * ATT_SCALE;
        sidx[warp][j] = kidx;
    }
    __syncwarp();

    float m = -1e30f;
    for (int j = lane; j < nk; j += 32) m = fmaxf(m, sc[warp][j]);
#pragma unroll
    for (int o = 16; o; o >>= 1) m = fmaxf(m, __shfl_xor_sync(0xffffffffu, m, o));

    float sum = 0.f;
    for (int j = lane; j < nk; j += 32) {
        float e = expf(sc[warp][j] - m);
        sc[warp][j] = e;
        sum += e;
    }
#pragma unroll
    for (int o = 16; o; o >>= 1) sum += __shfl_xor_sync(0xffffffffu, sum, o);
    __syncwarp();
    const float inv = 1.f / sum;

    float o0 = 0.f, o1 = 0.f;
    for (int j = 0; j < nk; j++) {
        float p = sc[warp][j];
        const float* vp = base + (size_t)sidx[warp][j] * (3 * DIM) + 2 * DIM + h * HDIM;
        o0 = fmaf(p, vp[2 * lane],     o0);
        o1 = fmaf(p, vp[2 * lane + 1], o1);
    }
    size_t ob = ((size_t)(b * SEQ + s)) * DIM + h * HDIM;
    __nv_bfloat16 h0, l0, h1, l1;
    split1(o0 * inv, h0, l0);
    split1(o1 * inv, h1, l1);
    *reinterpret_cast<uint32_t*>(outh + ob + 2 * lane) = pack_bf16(h0, h1);
    *reinterpret_cast<uint32_t*>(outl + ob + 2 * lane) = pack_bf16(l0, l1);
}

// ---------------- Patchify -> bf16 hi/lo ----------------
__global__ void patchify_kernel(const float* __restrict__ x,
                                __nv_bfloat16* __restrict__ xph, __nv_bfloat16* __restrict__ xpl)
{
    int idx = blockIdx.x * blockDim.x + threadIdx.x;
    const int total = NROWS_P * DIM;
    if (idx >= total) return;
    int e  = idx % DIM;
    int bp = idx / DIM;
    int p  = bp % NPATCH;
    int b  = bp / NPATCH;
    int c  = e / (PATCH * PATCH);
    int r  = e % (PATCH * PATCH);
    int py = r / PATCH, px = r % PATCH;
    int gy = p / GRID,  gx = p % GRID;
    float v = x[(((size_t)b * CHN + c) * IMG + gy * PATCH + py) * IMG + gx * PATCH + px];
    __nv_bfloat16 h, l;
    split1(v, h, l);
    xph[idx] = h;
    xpl[idx] = l;
}

// ---------------- Assemble ----------------
__global__ void assemble_kernel(const float* __restrict__ tok, const float* __restrict__ cls,
                                const float* __restrict__ pos, float* __restrict__ hout)
{
    int idx = blockIdx.x * blockDim.x + threadIdx.x;
    const int total = BATCH * SEQ * DIM;
    if (idx >= total) return;
    int d  = idx % DIM;
    int bs = idx / DIM;
    int s  = bs % SEQ;
    int b  = bs / SEQ;
    float v = (s == 0) ? cls[d] : tok[((size_t)b * NPATCH + (s - 1)) * DIM + d];
    hout[idx] = v + pos[(size_t)s * DIM + d];
}

// ---------------- host launcher ----------------
extern "C" void kernel_launch(void* const* d_in, const int* in_sizes, int n_in,
                              void* d_out, int out_size)
{
    const float* x        = (const float*)d_in[0];
    const float* patch_w  = (const float*)d_in[1];
    const float* patch_b  = (const float*)d_in[2];
    const float* cls_tok  = (const float*)d_in[3];
    const float* pos_emb  = (const float*)d_in[4];
    const float* qkv_w    = (const float*)d_in[5];
    const float* qkv_b    = (const float*)d_in[6];
    const float* proj_w   = (const float*)d_in[7];
    const float* proj_b   = (const float*)d_in[8];
    const float* ln1_s    = (const float*)d_in[9];
    const float* ln1_b    = (const float*)d_in[10];
    const float* ln2_s    = (const float*)d_in[11];
    const float* ln2_b    = (const float*)d_in[12];
    const float* fc1_w    = (const float*)d_in[13];
    const float* fc1_b    = (const float*)d_in[14];
    const float* fc2_w    = (const float*)d_in[15];
    const float* fc2_b    = (const float*)d_in[16];
    const int*   routes   = (const int*)d_in[17];

    float *hbuf, *qkv;
    __nv_bfloat16 *xnh, *xnl, *atth, *attl, *mlph, *mlpl, *wh, *wl;
    cudaGetSymbolAddress((void**)&hbuf, g_h);
    cudaGetSymbolAddress((void**)&qkv,  g_qkv);
    cudaGetSymbolAddress((void**)&xnh,  g_xnh);
    cudaGetSymbolAddress((void**)&xnl,  g_xnl);
    cudaGetSymbolAddress((void**)&atth, g_atth);
    cudaGetSymbolAddress((void**)&attl, g_attl);
    cudaGetSymbolAddress((void**)&mlph, g_mlph);
    cudaGetSymbolAddress((void**)&mlpl, g_mlpl);
    cudaGetSymbolAddress((void**)&wh,   g_wh);
    cudaGetSymbolAddress((void**)&wl,   g_wl);

    // smem: 2 stages. BM=128: 2*40960 = 81920 (2 CTAs/SM); BM=64: 2*30720 = 61440 (3 CTAs/SM)
    const int SMEM128 = 2 * (2 * 128 * 80 + 2 * 128 * 80);
    const int SMEM64  = 2 * (2 * 64 * 80 + 2 * 128 * 80);
    cudaFuncSetAttribute(hgemm<128, 0, 2>, cudaFuncAttributeMaxDynamicSharedMemorySize, SMEM128);
    cudaFuncSetAttribute(hgemm<64, 0, 3>,  cudaFuncAttributeMaxDynamicSharedMemorySize, SMEM64);
    cudaFuncSetAttribute(hgemm<64, 1, 3>,  cudaFuncAttributeMaxDynamicSharedMemorySize, SMEM64);
    cudaFuncSetAttribute(hgemm<64, 2, 3>,  cudaFuncAttributeMaxDynamicSharedMemorySize, SMEM64);

    // ---- one-time weight split ----
    {
        struct { const float* src; int off; int n; } cv[5] = {
            {patch_w, OFF_PATCH, NW_PATCH},
            {qkv_w,   OFF_QKV,   NW_QKV},
            {proj_w,  OFF_PROJ,  NW_PROJ},
            {fc1_w,   OFF_FC1,   NW_FC1},
            {fc2_w,   OFF_FC2,   NW_FC2},
        };
        for (int i = 0; i < 5; i++) {
            int n4 = cv[i].n / 4;
            cvt_weights<<<(n4 + 255) / 256, 256>>>(cv[i].src, wh + cv[i].off, wl + cv[i].off, n4);
        }
    }

    const int rt128 = (NROWS + 127) / 128;   // 13
    const int rt64  = (NROWS + 63) / 64;     // 25
    const int rt64p = (NROWS_P + 63) / 64;   // 25

    // patch embed
    {
        int tot = NROWS_P * DIM;
        patchify_kernel<<<(tot + 255) / 256, 256>>>(x, mlph, mlpl);
        hgemm<64, 0, 3><<<dim3(DIM / 128, rt64p), 128, SMEM64>>>(
            mlph, mlpl, wh + OFF_PATCH, wl + OFF_PATCH, patch_b, nullptr,
            qkv, nullptr, nullptr, NROWS_P, DIM, DIM);
        int tot2 = BATCH * SEQ * DIM;
        assemble_kernel<<<(tot2 + 255) / 256, 256>>>(qkv, cls_tok, pos_emb, hbuf);
    }

    for (int l = 0; l < NLAYER; l++) {
        const size_t oq  = OFF_QKV  + (size_t)l * 3 * DIM * DIM;
        const size_t op  = OFF_PROJ + (size_t)l * DIM * DIM;
        const size_t of1 = OFF_FC1  + (size_t)l * MLPDIM * DIM;
        const size_t of2 = OFF_FC2  + (size_t)l * DIM * MLPDIM;
        const float* qb  = qkv_b  + (size_t)l * 3 * DIM;
        const float* pb  = proj_b + (size_t)l * DIM;
        const float* f1b = fc1_b  + (size_t)l * MLPDIM;
        const float* f2b = fc2_b  + (size_t)l * DIM;

        ln_kernel<<<NROWS, 256>>>(hbuf, ln1_s + (size_t)l * DIM, ln1_b + (size_t)l * DIM,
                                  xnh, xnl);
        hgemm<128, 0, 2><<<dim3(3 * DIM / 128, rt128), 256, SMEM128>>>(
            xnh, xnl, wh + oq, wl + oq, qb, nullptr,
            qkv, nullptr, nullptr, NROWS, DIM, 3 * DIM);
        attn_kernel<<<dim3(BATCH * NHEAD, (SEQ + 3) / 4), 128>>>(qkv, routes, atth, attl);
        hgemm<64, 2, 3><<<dim3(DIM / 128, rt64), 128, SMEM64>>>(
            atth, attl, wh + op, wl + op, pb, hbuf,
            hbuf, nullptr, nullptr, NROWS, DIM, DIM);
        ln_kernel<<<NROWS, 256>>>(hbuf, ln2_s + (size_t)l * DIM, ln2_b + (size_t)l * DIM,
                                  xnh, xnl);
        hgemm<64, 1, 3><<<dim3(MLPDIM / 128, rt64), 128, SMEM64>>>(
            xnh, xnl, wh + of1, wl + of1, f1b, nullptr,
            nullptr, mlph, mlpl, NROWS, DIM, MLPDIM);
        float* outp = (l == NLAYER - 1) ? (float*)d_out : hbuf;
        hgemm<64, 2, 3><<<dim3(DIM / 128, rt64), 128, SMEM64>>>(
            mlph, mlpl, wh + of2, wl + of2, f2b, hbuf,
            outp, nullptr, nullptr, NROWS, MLPDIM, DIM);
    }
}